// round 9
// baseline (speedup 1.0000x reference)
#include <cuda_runtime.h>

// QuantizedTopKSparsity == out[r,c] = rint( x[r,c] / (max_c |x[r,c]| + 1e-6) )
// (quantized values are in {-1,0,+1}; the top-k mask is an identity on x_q).
//
// Final: the measured-optimal configuration (Round-5 structure):
//   - one 4096-float row per CTA, 256 threads, 2 x 256-bit LDG/STG per thread
//   - loads L2::evict_last, stores L2::evict_first
//   - 32 regs -> ~91% occupancy; DRAM-bound at ~75% of peak (5.9-6.0 TB/s),
//     which sweeps of block size / MLP / cache policy / persistence showed to
//     be the memory-path ceiling for this interleaved 1:1 R/W stream.
// Micro-opt vs R5: warp absmax via one REDUX.MAX.U32 (abs floats are
// non-negative, so float order == unsigned bit order) instead of 5 shuffles.

#define ROW_LEN 4096
#define THREADS 256
#define V8 2   // 2 x 8 floats = 16 floats per thread; 256*16 = 4096
#define NWARPS (THREADS / 32)

struct F8 { float a, b, c, d, e, f, g, h; };

__device__ __forceinline__ F8 ld_persist8(const void* p) {
    F8 v;
    asm volatile("ld.global.L2::evict_last.v8.b32 "
                 "{%0,%1,%2,%3,%4,%5,%6,%7}, [%8];"
                 : "=f"(v.a), "=f"(v.b), "=f"(v.c), "=f"(v.d),
                   "=f"(v.e), "=f"(v.f), "=f"(v.g), "=f"(v.h)
                 : "l"(p));
    return v;
}

__device__ __forceinline__ void st_stream8(void* p, const F8& v) {
    asm volatile("st.global.L2::evict_first.v8.b32 "
                 "[%0], {%1,%2,%3,%4,%5,%6,%7,%8};"
                 :: "l"(p),
                    "f"(v.a), "f"(v.b), "f"(v.c), "f"(v.d),
                    "f"(v.e), "f"(v.f), "f"(v.g), "f"(v.h)
                 : "memory");
}

__device__ __forceinline__ float absmax8(const F8& v) {
    float m0 = fmaxf(fmaxf(fabsf(v.a), fabsf(v.b)), fmaxf(fabsf(v.c), fabsf(v.d)));
    float m1 = fmaxf(fmaxf(fabsf(v.e), fabsf(v.f)), fmaxf(fabsf(v.g), fabsf(v.h)));
    return fmaxf(m0, m1);
}

__device__ __forceinline__ F8 quant8(const F8& v, float inv) {
    F8 o;
    o.a = rintf(v.a * inv); o.b = rintf(v.b * inv);
    o.c = rintf(v.c * inv); o.d = rintf(v.d * inv);
    o.e = rintf(v.e * inv); o.f = rintf(v.f * inv);
    o.g = rintf(v.g * inv); o.h = rintf(v.h * inv);
    return o;
}

__global__ __launch_bounds__(THREADS)
void qtopk_kernel(const float* __restrict__ x, float* __restrict__ out, int rows) {
    const int row = blockIdx.x;
    if (row >= rows) return;

    const float* __restrict__ xr = x   + (size_t)row * ROW_LEN;
    float* __restrict__ orr      = out + (size_t)row * ROW_LEN;

    const int t = threadIdx.x;

    // Two 256-bit persisting loads per thread, coalesced 32B stripes.
    F8 v[V8];
#pragma unroll
    for (int i = 0; i < V8; i++)
        v[i] = ld_persist8(xr + (t + i * THREADS) * 8);

    float m = 0.0f;
#pragma unroll
    for (int i = 0; i < V8; i++) m = fmaxf(m, absmax8(v[i]));

    // Warp absmax: abs floats are non-negative, so unsigned bit-pattern max
    // equals float max -> single REDUX.MAX.U32.
    m = __uint_as_float(__reduce_max_sync(0xffffffffu, __float_as_uint(m)));

    // Cross-warp absmax via smem (8 warps).
    __shared__ float smax[NWARPS];
    if ((t & 31) == 0) smax[t >> 5] = m;
    __syncthreads();

    float g = smax[0];
#pragma unroll
    for (int w = 1; w < NWARPS; w++) g = fmaxf(g, smax[w]);

    const float inv = 1.0f / (g + 1e-6f);

    // Quantize from registers; 256-bit evict-first stores.
#pragma unroll
    for (int i = 0; i < V8; i++)
        st_stream8(orr + (t + i * THREADS) * 8, quant8(v[i], inv));
}

extern "C" void kernel_launch(void* const* d_in, const int* in_sizes, int n_in,
                              void* d_out, int out_size) {
    const float* x = (const float*)d_in[0];
    float* out = (float*)d_out;
    const int rows = in_sizes[0] / ROW_LEN;   // 8192
    qtopk_kernel<<<rows, THREADS>>>(x, out, rows);
}